// round 1
// baseline (speedup 1.0000x reference)
#include <cuda_runtime.h>
#include <math.h>

// Problem constants
#define B_  8
#define S_  2048
#define T_  128
#define BS_ (B_*S_)

#define MTILE 128          // rows (b,s) per block
#define PADR  132          // padded row stride (floats) for smem arrays
#define SMEM_BYTES (3 * T_ * PADR * 4)   // tokT + hT + Wsh = 202,752 B

// Scratch: W transposed to [p][q][t] so per-p staging loads are contiguous.
__device__ float g_WT[T_ * T_ * T_];     // 8 MB
__device__ float g_base[T_];

// ---------------------------------------------------------------------------
// Kernel 1: transpose W[t][p][q] -> g_WT[p][q][t]
// ---------------------------------------------------------------------------
__global__ void k_transpose_W(const float* __restrict__ W) {
    __shared__ float tile[32][33];
    int p  = blockIdx.z;
    int t0 = blockIdx.x * 32;
    int q0 = blockIdx.y * 32;
    int tx = threadIdx.x;   // 0..31
    int ty = threadIdx.y;   // 0..7
    #pragma unroll
    for (int i = ty; i < 32; i += 8)
        tile[i][tx] = W[(size_t)(t0 + i) * (T_ * T_) + p * T_ + q0 + tx];
    __syncthreads();
    #pragma unroll
    for (int i = ty; i < 32; i += 8)
        g_WT[(size_t)p * (T_ * T_) + (size_t)(q0 + i) * T_ + t0 + tx] = tile[tx][i];
}

// ---------------------------------------------------------------------------
// Kernel 2: base[t] = (sum_j w_red[j]) * tanh(b_comp[t]) + b_red[0]
// ---------------------------------------------------------------------------
__global__ void k_compute_base(const float* __restrict__ w_red,
                               const float* __restrict__ b_red,
                               const float* __restrict__ b_comp) {
    __shared__ float sbuf[256];
    int tid = threadIdx.x;
    float s = 0.f;
    for (int i = tid; i < S_; i += 256) s += w_red[i];
    sbuf[tid] = s;
    __syncthreads();
    for (int st = 128; st > 0; st >>= 1) {
        if (tid < st) sbuf[tid] += sbuf[tid + st];
        __syncthreads();
    }
    float sumw = sbuf[0];
    if (tid < T_) g_base[tid] = sumw * tanhf(b_comp[tid]) + b_red[0];
}

// ---------------------------------------------------------------------------
// Kernel 3: out[b,i,t] = base[t]   (scatter target baseline)
// ---------------------------------------------------------------------------
__global__ void k_fill_out(float* __restrict__ out) {
    int i = blockIdx.x * 256 + threadIdx.x;
    if (i < BS_ * T_) out[i] = g_base[i & (T_ - 1)];
}

// ---------------------------------------------------------------------------
// Kernel 4: main bilinear + tanh + weighted scatter-add.
// Per block: 128 rows (b, s0..s0+127) x all 128 t.
//   val[m,t] = sum_p tok[m,p] * sum_q h[m,q] * W[t,p,q]
// A-chunk for fixed p is rank-1: tok[m,p] * h[m,:], built on the fly.
// ---------------------------------------------------------------------------
__global__ __launch_bounds__(256, 1)
void k_main(const float* __restrict__ tok,
            const int*   __restrict__ heads,
            const float* __restrict__ b_comp,
            const float* __restrict__ w_red,
            float*       __restrict__ out) {
    extern __shared__ float smem[];
    float* tokT = smem;                 // [p][m]  stride PADR
    float* hT   = smem + T_ * PADR;     // [q][m]  stride PADR
    float* Wsh  = smem + 2 * T_ * PADR; // [q][t]  stride PADR

    int tid = threadIdx.x;
    int bb  = blockIdx.x >> 4;            // batch
    int s0  = (blockIdx.x & 15) * MTILE;  // row tile start
    const float* tokbase = tok + ((size_t)bb * S_ + s0) * T_;

    // --- init: load token tile once; fill tokT (transposed) and hT = tanh ---
    #pragma unroll
    for (int k = 0; k < 16; k++) {
        int f4 = tid + k * 256;       // 0..4095 float4 slots
        int m  = f4 >> 5;             // row 0..127
        int c4 = f4 & 31;             // col/4
        float4 v = *(const float4*)(tokbase + m * T_ + c4 * 4);
        int col = c4 * 4;
        tokT[(col + 0) * PADR + m] = v.x;  hT[(col + 0) * PADR + m] = tanhf(v.x);
        tokT[(col + 1) * PADR + m] = v.y;  hT[(col + 1) * PADR + m] = tanhf(v.y);
        tokT[(col + 2) * PADR + m] = v.z;  hT[(col + 2) * PADR + m] = tanhf(v.z);
        tokT[(col + 3) * PADR + m] = v.w;  hT[(col + 3) * PADR + m] = tanhf(v.w);
    }

    int ty = tid >> 4, tx = tid & 15;
    int m0 = ty * 8, t0 = tx * 8;

    float acc[8][8];
    #pragma unroll
    for (int i = 0; i < 8; i++)
        #pragma unroll
        for (int j = 0; j < 8; j++) acc[i][j] = 0.f;

    #pragma unroll 1
    for (int p = 0; p < T_; p++) {
        __syncthreads();   // previous Wsh consumers done (also covers init on p==0)
        // stage W[:, p, :] as Wsh[q][t] from pre-transposed g_WT (contiguous)
        const float4* wsrc = (const float4*)(g_WT + (size_t)p * (T_ * T_));
        #pragma unroll
        for (int k = 0; k < 16; k++) {
            int f4 = tid + k * 256;
            int q  = f4 >> 5;
            int tv = f4 & 31;
            *(float4*)(Wsh + q * PADR + tv * 4) = wsrc[f4];
        }
        __syncthreads();

        float tokr[8];
        #pragma unroll
        for (int i = 0; i < 8; i++) tokr[i] = tokT[p * PADR + m0 + i];

        const float* hp = hT  + m0;
        const float* wp = Wsh + t0;
        #pragma unroll 4
        for (int q = 0; q < T_; q++) {
            float4 h0 = *(const float4*)(hp);
            float4 h1 = *(const float4*)(hp + 4);
            float4 w0 = *(const float4*)(wp);
            float4 w1 = *(const float4*)(wp + 4);
            hp += PADR; wp += PADR;
            float a[8] = { h0.x * tokr[0], h0.y * tokr[1], h0.z * tokr[2], h0.w * tokr[3],
                           h1.x * tokr[4], h1.y * tokr[5], h1.z * tokr[6], h1.w * tokr[7] };
            float w[8] = { w0.x, w0.y, w0.z, w0.w, w1.x, w1.y, w1.z, w1.w };
            #pragma unroll
            for (int i = 0; i < 8; i++)
                #pragma unroll
                for (int j = 0; j < 8; j++)
                    acc[i][j] += a[i] * w[j];
        }
    }

    // --- epilogue: act = tanh(val + b_comp); scatter w_red[s]*(act - tanh(b_comp)) ---
    float wr[8]; int hd[8];
    #pragma unroll
    for (int i = 0; i < 8; i++) {
        int srow = s0 + m0 + i;
        wr[i] = w_red[srow];
        hd[i] = heads[bb * S_ + srow];
    }
    #pragma unroll
    for (int j = 0; j < 8; j++) {
        float bj = b_comp[t0 + j];
        float bv = tanhf(bj);
        #pragma unroll
        for (int i = 0; i < 8; i++) {
            float act = tanhf(acc[i][j] + bj);
            float contrib = wr[i] * (act - bv);
            atomicAdd(&out[((size_t)bb * S_ + hd[i]) * T_ + t0 + j], contrib);
        }
    }
}

// ---------------------------------------------------------------------------
extern "C" void kernel_launch(void* const* d_in, const int* in_sizes, int n_in,
                              void* d_out, int out_size) {
    (void)in_sizes; (void)n_in; (void)out_size;
    const float* tok    = (const float*)d_in[0];
    // d_in[1] = dep_embeddings: dead input (source bug), unused
    const int*   heads  = (const int*)  d_in[2];
    const float* W      = (const float*)d_in[3];
    const float* b_comp = (const float*)d_in[4];
    const float* w_red  = (const float*)d_in[5];
    const float* b_red  = (const float*)d_in[6];
    float* out = (float*)d_out;

    cudaFuncSetAttribute(k_main, cudaFuncAttributeMaxDynamicSharedMemorySize, SMEM_BYTES);

    k_transpose_W<<<dim3(4, 4, 128), dim3(32, 8)>>>(W);
    k_compute_base<<<1, 256>>>(w_red, b_red, b_comp);
    k_fill_out<<<(BS_ * T_) / 256, 256>>>(out);
    k_main<<<128, 256, SMEM_BYTES>>>(tok, heads, b_comp, w_red, out);
}

// round 5
// speedup vs baseline: 3.2342x; 3.2342x over previous
#include <cuda_runtime.h>
#include <cuda_bf16.h>
#include <cstdint>
#include <math.h>

// Problem constants
#define B_  8
#define S_  2048
#define T_  128
#define BS_ (B_*S_)

#define AST 272                  // padded SMEM/global row stride in bytes (136 bf16)
#define TILE_BYTES (128*AST)     // 34816 bytes per 128x128 bf16 tile

// ---------------------------------------------------------------------------
// Device scratch (__device__ globals: allocation-free rule)
// ---------------------------------------------------------------------------
__device__ char  g_Whi[128 * TILE_BYTES];   // per p: W[:,p,:] hi, padded rows
__device__ char  g_Wlo[128 * TILE_BYTES];   // per p: W[:,p,:] lo
__device__ float g_tokT[(size_t)B_ * T_ * S_];      // tok transposed [b][p][s]
__device__ float g_base[T_];

// ---------------------------------------------------------------------------
// SMEM layout (bytes)
// ---------------------------------------------------------------------------
#define SM_AHI 0
#define SM_ALO TILE_BYTES
#define STAGE_BYTES (2*TILE_BYTES + 512)            // Bhi + Blo + tok column
#define SM_BST(s)  (2*TILE_BYTES + (s)*STAGE_BYTES)
#define SM_BC  (2*TILE_BYTES + 2*STAGE_BYTES)       // b_comp[128]
#define SM_TB  (SM_BC + 512)                        // tanh(b_comp)[128]
#define SMEM_TOTAL (SM_TB + 512)                    // 210944

// ---------------------------------------------------------------------------
// PTX helpers (sm_80-era only: compiles for base sm_103 target)
// ---------------------------------------------------------------------------
__device__ __forceinline__ uint32_t smem_u32(const void* p) {
    uint32_t a;
    asm("{ .reg .u64 t; cvta.to.shared.u64 t, %1; cvt.u32.u64 %0, t; }" : "=r"(a) : "l"(p));
    return a;
}
__device__ __forceinline__ void cp16(uint32_t dst, const void* src) {
    asm volatile("cp.async.cg.shared.global [%0], [%1], 16;" :: "r"(dst), "l"(src) : "memory");
}
__device__ __forceinline__ void cp_commit() {
    asm volatile("cp.async.commit_group;" ::: "memory");
}
__device__ __forceinline__ void cp_wait1() {
    asm volatile("cp.async.wait_group 1;" ::: "memory");
}
__device__ __forceinline__ void ldsm4(uint32_t* r, uint32_t addr) {
    asm volatile("ldmatrix.sync.aligned.m8n8.x4.shared.b16 {%0,%1,%2,%3}, [%4];"
        : "=r"(r[0]), "=r"(r[1]), "=r"(r[2]), "=r"(r[3]) : "r"(addr));
}
__device__ __forceinline__ void mma_bf16(float* d, const uint32_t* a, const uint32_t* b) {
    asm volatile(
        "mma.sync.aligned.m16n8k16.row.col.f32.bf16.bf16.f32 "
        "{%0,%1,%2,%3}, {%4,%5,%6,%7}, {%8,%9}, {%0,%1,%2,%3};"
        : "+f"(d[0]), "+f"(d[1]), "+f"(d[2]), "+f"(d[3])
        : "r"(a[0]), "r"(a[1]), "r"(a[2]), "r"(a[3]), "r"(b[0]), "r"(b[1]));
}
__device__ __forceinline__ uint32_t pack_bf2(float a, float b) {
    __nv_bfloat162 t;
    t.x = __float2bfloat16_rn(a);
    t.y = __float2bfloat16_rn(b);
    return *(uint32_t*)&t;
}

// ---------------------------------------------------------------------------
// Prep: W[t][p][q] -> g_Whi/g_Wlo[p][t][q], bf16 split, padded 272B rows
// ---------------------------------------------------------------------------
__global__ void k_prep_W(const float* __restrict__ W) {
    int p = blockIdx.x;
    char* hb = g_Whi + (size_t)p * TILE_BYTES;
    char* lb = g_Wlo + (size_t)p * TILE_BYTES;
    for (int i = threadIdx.x; i < 16384; i += 256) {
        int t = i >> 7, q = i & 127;
        float w = W[(size_t)t * 16384 + p * 128 + q];
        __nv_bfloat16 hi = __float2bfloat16_rn(w);
        __nv_bfloat16 lo = __float2bfloat16_rn(w - __bfloat162float(hi));
        *(__nv_bfloat16*)(hb + t * AST + q * 2) = hi;
        *(__nv_bfloat16*)(lb + t * AST + q * 2) = lo;
    }
    for (int i = threadIdx.x; i < 128 * 8; i += 256) {   // zero row padding
        int t = i >> 3, j = i & 7;
        *(__nv_bfloat16*)(hb + t * AST + 256 + j * 2) = __float2bfloat16_rn(0.f);
        *(__nv_bfloat16*)(lb + t * AST + 256 + j * 2) = __float2bfloat16_rn(0.f);
    }
}

// tok [b][s][p] -> g_tokT [b][p][s]
__global__ void k_prep_tokT(const float* __restrict__ tok) {
    __shared__ float tile[32][33];
    int b = blockIdx.z;
    int sblk = blockIdx.x * 32, pblk = blockIdx.y * 32;
    int tx = threadIdx.x, ty = threadIdx.y;
    #pragma unroll
    for (int i = ty; i < 32; i += 8)
        tile[i][tx] = tok[((size_t)b * S_ + sblk + i) * T_ + pblk + tx];
    __syncthreads();
    #pragma unroll
    for (int i = ty; i < 32; i += 8)
        g_tokT[((size_t)b * T_ + pblk + i) * S_ + sblk + tx] = tile[tx][i];
}

__global__ void k_compute_base(const float* __restrict__ w_red,
                               const float* __restrict__ b_red,
                               const float* __restrict__ b_comp) {
    __shared__ float sbuf[256];
    int tid = threadIdx.x;
    float s = 0.f;
    for (int i = tid; i < S_; i += 256) s += w_red[i];
    sbuf[tid] = s;
    __syncthreads();
    for (int st = 128; st > 0; st >>= 1) {
        if (tid < st) sbuf[tid] += sbuf[tid + st];
        __syncthreads();
    }
    if (tid < T_) g_base[tid] = sbuf[0] * tanhf(b_comp[tid]) + b_red[0];
}

__global__ void k_fill_out(float* __restrict__ out) {
    int i = blockIdx.x * 256 + threadIdx.x;
    if (i < BS_ * T_) out[i] = g_base[i & (T_ - 1)];
}

// ---------------------------------------------------------------------------
// Main kernel: 128 CTAs x 256 threads; CTA = 128 token rows x 128 t cols.
// ---------------------------------------------------------------------------
__global__ __launch_bounds__(256, 1)
void k_main(const float* __restrict__ tok,
            const int*   __restrict__ heads,
            const float* __restrict__ b_comp,
            const float* __restrict__ w_red,
            float*       __restrict__ out) {
    extern __shared__ char smem[];
    uint32_t sb = smem_u32(smem);
    int tid = threadIdx.x, lane = tid & 31, wid = tid >> 5;
    int bb = blockIdx.x >> 4;
    int s0 = (blockIdx.x & 15) * 128;
    int m0 = (wid & 3) * 32;       // warp m-tile
    int n0 = (wid >> 2) * 64;      // warp n-tile

    if (tid < 128) {
        float bc = b_comp[tid];
        *(float*)(smem + SM_BC + tid * 4) = bc;
        *(float*)(smem + SM_TB + tid * 4) = tanhf(bc);
    }

    // --- build static A: hi/lo bf16 split of tanh(tok tile), [m][q] 272B rows
    const float* tokbase = tok + ((size_t)bb * S_ + s0) * T_;
    for (int g = tid; g < 2048; g += 256) {
        int m = g >> 4, q0 = (g & 15) * 8;
        float4 v0 = *(const float4*)(tokbase + m * T_ + q0);
        float4 v1 = *(const float4*)(tokbase + m * T_ + q0 + 4);
        float f[8] = {v0.x, v0.y, v0.z, v0.w, v1.x, v1.y, v1.z, v1.w};
        float h[8], hi[8];
        #pragma unroll
        for (int j = 0; j < 8; j++) {
            h[j]  = tanhf(f[j]);
            hi[j] = __bfloat162float(__float2bfloat16_rn(h[j]));
        }
        uint4 uh, ul;
        uh.x = pack_bf2(h[0], h[1]); uh.y = pack_bf2(h[2], h[3]);
        uh.z = pack_bf2(h[4], h[5]); uh.w = pack_bf2(h[6], h[7]);
        ul.x = pack_bf2(h[0]-hi[0], h[1]-hi[1]); ul.y = pack_bf2(h[2]-hi[2], h[3]-hi[3]);
        ul.z = pack_bf2(h[4]-hi[4], h[5]-hi[5]); ul.w = pack_bf2(h[6]-hi[6], h[7]-hi[7]);
        *(uint4*)(smem + SM_AHI + m * AST + q0 * 2) = uh;
        *(uint4*)(smem + SM_ALO + m * AST + q0 * 2) = ul;
    }

    // --- prologue: stage copies for p=0,1 (cp.async double buffer)
    #pragma unroll
    for (int pp = 0; pp < 2; pp++) {
        uint32_t dst = sb + SM_BST(pp);
        const char* srch = g_Whi + (size_t)pp * TILE_BYTES;
        const char* srcl = g_Wlo + (size_t)pp * TILE_BYTES;
        for (int i = tid; i < TILE_BYTES / 16; i += 256) {
            cp16(dst + i * 16, srch + i * 16);
            cp16(dst + TILE_BYTES + i * 16, srcl + i * 16);
        }
        if (tid < 32)
            cp16(dst + 2 * TILE_BYTES + tid * 16,
                 (const char*)g_tokT + (((size_t)bb * T_ + pp) * S_ + s0) * 4 + tid * 16);
        cp_commit();
    }
    __syncthreads();   // A + bc/tb visible

    // --- lane-fixed ldmatrix address components
    uint32_t aAddrHi = sb + SM_AHI + (uint32_t)(m0 + (lane & 15)) * AST + ((lane >> 4) << 4);
    uint32_t aAddrLo = aAddrHi + TILE_BYTES;
    uint32_t bRowOff = (uint32_t)(n0 + ((lane >> 4) << 3) + (lane & 7)) * AST
                     + ((lane >> 3) & 1) * 16;

    float val[2][8][4];
    #pragma unroll
    for (int mf = 0; mf < 2; mf++)
        #pragma unroll
        for (int nf = 0; nf < 8; nf++)
            #pragma unroll
            for (int e = 0; e < 4; e++) val[mf][nf][e] = 0.f;

    #pragma unroll 1
    for (int p = 0; p < 128; p++) {
        int s = p & 1;
        cp_wait1();
        __syncthreads();

        uint32_t bhi = sb + SM_BST(s) + bRowOff;
        uint32_t blo = bhi + TILE_BYTES;

        float g[2][8][4];
        #pragma unroll
        for (int mf = 0; mf < 2; mf++)
            #pragma unroll
            for (int nf = 0; nf < 8; nf++)
                #pragma unroll
                for (int e = 0; e < 4; e++) g[mf][nf][e] = 0.f;

        #pragma unroll
        for (int ks = 0; ks < 8; ks++) {
            uint32_t ao = ks * 32;
            uint32_t Ah0[4], Ah1[4], Al0[4], Al1[4];
            ldsm4(Ah0, aAddrHi + ao);
            ldsm4(Ah1, aAddrHi + 16 * AST + ao);
            ldsm4(Al0, aAddrLo + ao);
            ldsm4(Al1, aAddrLo + 16 * AST + ao);
            uint32_t Bh[16], Bl[16];
            #pragma unroll
            for (int nf2 = 0; nf2 < 4; nf2++) {
                ldsm4(&Bh[nf2 * 4], bhi + nf2 * 16 * AST + ao);
                ldsm4(&Bl[nf2 * 4], blo + nf2 * 16 * AST + ao);
            }
            // product 1: A_hi x B_hi
            #pragma unroll
            for (int nf = 0; nf < 8; nf++) {
                const uint32_t* bf = &Bh[(nf >> 1) * 4 + (nf & 1) * 2];
                mma_bf16(g[0][nf], Ah0, bf);
                mma_bf16(g[1][nf], Ah1, bf);
            }
            // product 2: A_lo x B_hi
            #pragma unroll
            for (int nf = 0; nf < 8; nf++) {
                const uint32_t* bf = &Bh[(nf >> 1) * 4 + (nf & 1) * 2];
                mma_bf16(g[0][nf], Al0, bf);
                mma_bf16(g[1][nf], Al1, bf);
            }
            // product 3: A_hi x B_lo
            #pragma unroll
            for (int nf = 0; nf < 8; nf++) {
                const uint32_t* bf = &Bl[(nf >> 1) * 4 + (nf & 1) * 2];
                mma_bf16(g[0][nf], Ah0, bf);
                mma_bf16(g[1][nf], Ah1, bf);
            }
        }

        // scale-accumulate: val += tok[m,p] * G
        const float* tcol = (const float*)(smem + SM_BST(s) + 2 * TILE_BYTES);
        int rbase = m0 + (lane >> 2);
        float tv[4];
        #pragma unroll
        for (int j = 0; j < 4; j++) tv[j] = tcol[rbase + j * 8];   // rows +0,+8,+16,+24
        #pragma unroll
        for (int mf = 0; mf < 2; mf++)
            #pragma unroll
            for (int nf = 0; nf < 8; nf++)
                #pragma unroll
                for (int e = 0; e < 4; e++)
                    val[mf][nf][e] = fmaf(tv[mf * 2 + (e >> 1)], g[mf][nf][e], val[mf][nf][e]);

        __syncthreads();   // all warps done reading stage s before overwrite

        if (p + 2 < 128) {
            uint32_t dst = sb + SM_BST(s);
            const char* srch = g_Whi + (size_t)(p + 2) * TILE_BYTES;
            const char* srcl = g_Wlo + (size_t)(p + 2) * TILE_BYTES;
            for (int i = tid; i < TILE_BYTES / 16; i += 256) {
                cp16(dst + i * 16, srch + i * 16);
                cp16(dst + TILE_BYTES + i * 16, srcl + i * 16);
            }
            if (tid < 32)
                cp16(dst + 2 * TILE_BYTES + tid * 16,
                     (const char*)g_tokT + (((size_t)bb * T_ + p + 2) * S_ + s0) * 4 + tid * 16);
        }
        cp_commit();
    }

    // --- epilogue: act = tanh(val + bc); scatter w_red*(act - tanh(bc))
    const float* bcv = (const float*)(smem + SM_BC);
    const float* tbv = (const float*)(smem + SM_TB);
    int r0 = m0 + (lane >> 2);
    #pragma unroll
    for (int mf = 0; mf < 2; mf++)
        #pragma unroll
        for (int eh = 0; eh < 2; eh++) {
            int rl = r0 + mf * 16 + eh * 8;
            int srow = s0 + rl;
            float wr = w_red[srow];
            int hd = heads[bb * S_ + srow];
            float* orow = out + ((size_t)bb * S_ + hd) * T_;
            #pragma unroll
            for (int nf = 0; nf < 8; nf++)
                #pragma unroll
                for (int ec = 0; ec < 2; ec++) {
                    int col = n0 + nf * 8 + (lane & 3) * 2 + ec;
                    float act = tanhf(val[mf][nf][eh * 2 + ec] + bcv[col]);
                    atomicAdd(orow + col, wr * (act - tbv[col]));
                }
        }
}

// ---------------------------------------------------------------------------
extern "C" void kernel_launch(void* const* d_in, const int* in_sizes, int n_in,
                              void* d_out, int out_size) {
    (void)in_sizes; (void)n_in; (void)out_size;
    const float* tok    = (const float*)d_in[0];
    // d_in[1] = dep_embeddings: dead input (source bug), unused
    const int*   heads  = (const int*)  d_in[2];
    const float* W      = (const float*)d_in[3];
    const float* b_comp = (const float*)d_in[4];
    const float* w_red  = (const float*)d_in[5];
    const float* b_red  = (const float*)d_in[6];
    float* out = (float*)d_out;

    cudaFuncSetAttribute(k_main, cudaFuncAttributeMaxDynamicSharedMemorySize, SMEM_TOTAL);

    k_prep_W<<<128, 256>>>(W);
    k_prep_tokT<<<dim3(64, 4, 8), dim3(32, 8)>>>(tok);
    k_compute_base<<<1, 256>>>(w_red, b_red, b_comp);
    k_fill_out<<<(BS_ * T_) / 256, 256>>>(out);
    k_main<<<128, 256, SMEM_TOTAL>>>(tok, heads, b_comp, w_red, out);
}